// round 16
// baseline (speedup 1.0000x reference)
#include <cuda_runtime.h>
#include <cstdint>

// Inputs (metadata order):
//   d_in[0] state           float32 [B, A, N, 3]
//   d_in[1] nodes_coords    float32 [P, 2]
//   d_in[2] adj             float32 [P, N]
//   d_in[3] node_last_visit int32   [B, A]
//   d_in[4] patrol_index    int32   [P]
// Output: float32 [B, A, N, 6]
//
// One CTA per row, block=64 (2 warps -> 32 CTAs/SM = 100% warp occupancy).
// Each WARP is an independent pipeline over chunks of 32 node pairs:
// LDG -> STS.128 -> per-warp TMA bulk store; chunk 2's loads overlap chunk 1's
// store drain. No __syncthreads anywhere.

__global__ __launch_bounds__(64)
void policy_gather_kernel(const float* __restrict__ state,
                          const float* __restrict__ coords,
                          const float* __restrict__ adj,
                          const int*   __restrict__ nlv,
                          const int*   __restrict__ pidx,
                          float* __restrict__ out,
                          int N) {
    extern __shared__ __align__(16) float s_row[];   // N*6 floats, output-row image

    const int row  = blockIdx.x;
    const int t    = threadIdx.x;
    const int warp = t >> 5;
    const int lane = t & 31;

    // Row-constant gathers (L1/L2 resident, broadcast).
    const int   v   = __ldg(nlv + row);
    const int   idx = __ldg(pidx + v);
    const float zx  = __ldg(coords + 2 * v);
    const float zy  = __ldg(coords + 2 * v + 1);

    const float* __restrict__ st = state + (size_t)row * N * 3;   // 8B aligned
    const float* __restrict__ ar = adj   + (size_t)idx * N;       // 8B aligned
    float* __restrict__ orow     = out   + (size_t)row * N * 6;   // 16B aligned

    const bool okA   = (((((uintptr_t)st) | ((uintptr_t)ar)) & 7) == 0);
    const bool okTMA = ((((uintptr_t)orow) & 0xF) == 0);

    if (okA && okTMA) {
        const int pairs = N >> 1;

        // Each warp: independent chunks of 32 pairs, stride 64 (2 warps).
        for (int start = warp * 32; start < pairs; start += 64) {
            const int cnt = min(32, pairs - start);
            const int p   = start + lane;

            if (lane < cnt) {
                const float2 s01 = __ldcs(reinterpret_cast<const float2*>(st + 6 * p));
                const float2 s23 = __ldcs(reinterpret_cast<const float2*>(st + 6 * p + 2));
                const float2 s45 = __ldcs(reinterpret_cast<const float2*>(st + 6 * p + 4));
                const float2 aa  = __ldg (reinterpret_cast<const float2*>(ar + 2 * p));

                float4* d = reinterpret_cast<float4*>(s_row + 12 * p);  // 16B aligned
                d[0] = make_float4(s01.x, s01.y, s23.x, zx);
                d[1] = make_float4(zy,    aa.x,  s23.y, s45.x);
                d[2] = make_float4(s45.y, zx,    zy,    aa.y);
            }
            __syncwarp();
            // Order this warp's generic smem writes before the async-proxy read.
            asm volatile("fence.proxy.async.shared::cta;" ::: "memory");

            if (lane == 0) {
                const unsigned bytes = (unsigned)(cnt * 12 * sizeof(float));  // mult of 48
                float* gdst = orow + (size_t)start * 12;
                uint32_t saddr;
                asm("{ .reg .u64 tmp; cvta.to.shared.u64 tmp, %1; cvt.u32.u64 %0, tmp; }"
                    : "=r"(saddr) : "l"(s_row + 12 * start));
                asm volatile(
                    "cp.async.bulk.global.shared::cta.bulk_group [%0], [%1], %2;"
                    :: "l"(gdst), "r"(saddr), "r"(bytes) : "memory");
                asm volatile("cp.async.bulk.commit_group;" ::: "memory");
            }
        }

        // Odd-N tail node: direct scalar global stores.
        if ((N & 1) && t == 0) {
            const int n = N - 1;
            float* d = orow + 6 * n;
            __stcs(d + 0, st[3 * n + 0]);
            __stcs(d + 1, st[3 * n + 1]);
            __stcs(d + 2, st[3 * n + 2]);
            __stcs(d + 3, zx);
            __stcs(d + 4, zy);
            __stcs(d + 5, ar[n]);
        }

        // Exit gate: only smem READ completion must precede smem release.
        if (lane == 0) {
            asm volatile("cp.async.bulk.wait_group.read 0;" ::: "memory");
        }
    } else {
        // Fallback: staged scalar copy with full-block sync.
        for (int n = t; n < N; n += blockDim.x) {
            float* d = s_row + 6 * n;
            d[0] = st[3 * n + 0];
            d[1] = st[3 * n + 1];
            d[2] = st[3 * n + 2];
            d[3] = zx;
            d[4] = zy;
            d[5] = ar[n];
        }
        __syncthreads();
        const int total = N * 6;
        for (int j = t; j < total; j += blockDim.x) {
            __stcs(orow + j, s_row[j]);
        }
    }
}

extern "C" void kernel_launch(void* const* d_in, const int* in_sizes, int n_in,
                              void* d_out, int out_size) {
    const float* state  = (const float*)d_in[0];
    const float* coords = (const float*)d_in[1];
    const float* adj    = (const float*)d_in[2];
    const int*   nlv    = (const int*)d_in[3];
    const int*   pidx   = (const int*)d_in[4];
    float*       out    = (float*)d_out;

    const int BA = in_sizes[3];            // B * A rows
    const int P  = in_sizes[4];            // patrol nodes
    const int N  = in_sizes[2] / P;        // graph size (adj is [P, N])

    const size_t smem = (size_t)N * 6 * sizeof(float);
    policy_gather_kernel<<<BA, 64, smem>>>(state, coords, adj, nlv, pidx, out, N);
}

// round 17
// speedup vs baseline: 1.1645x; 1.1645x over previous
#include <cuda_runtime.h>
#include <cstdint>

// Inputs (metadata order):
//   d_in[0] state           float32 [B, A, N, 3]
//   d_in[1] nodes_coords    float32 [P, 2]
//   d_in[2] adj             float32 [P, N]
//   d_in[3] node_last_visit int32   [B, A]
//   d_in[4] patrol_index    int32   [P]
// Output: float32 [B, A, N, 6]
//
// Best-known design (R10/R13): one CTA per row, 128 threads; each WARP is a
// fully independent pipeline over its contiguous slice of 32 node pairs:
//   strided LDG.64 gather -> STS.128 into an output-image smem tile ->
//   per-warp cp.async.bulk (TMA) store of its 1536B slice.
// No __syncthreads; exit gated only on bulk-read completion.
// Micro-opts: state loads issued before the nlv->pidx->coords chain;
// speculative L1 prefetch of the adj row off v.

__global__ __launch_bounds__(128)
void policy_gather_kernel(const float* __restrict__ state,
                          const float* __restrict__ coords,
                          const float* __restrict__ adj,
                          const int*   __restrict__ nlv,
                          const int*   __restrict__ pidx,
                          float* __restrict__ out,
                          int N) {
    extern __shared__ __align__(16) float s_row[];   // N*6 floats, output-row image

    const int row  = blockIdx.x;
    const int t    = threadIdx.x;
    const int warp = t >> 5;
    const int lane = t & 31;

    const float* __restrict__ st = state + (size_t)row * N * 3;   // 8B aligned
    float* __restrict__ orow     = out   + (size_t)row * N * 6;   // 16B aligned

    const bool okA   = ((((uintptr_t)st) & 7) == 0) && ((((uintptr_t)adj) & 7) == 0);
    const bool okTMA = ((((uintptr_t)orow) & 0xF) == 0);
    const int pairs  = N >> 1;

    if (okA && okTMA && pairs <= 128) {
        const int start = warp * 32;
        const int cnt   = pairs - start;            // lanes < cnt are active
        const int p     = start + lane;
        const bool act  = (lane < cnt);

        // Independent state loads FIRST: their DRAM latency overlaps the
        // row-constant chain below.
        float2 s01 = make_float2(0.f, 0.f), s23 = s01, s45 = s01;
        if (act) {
            s01 = __ldcs(reinterpret_cast<const float2*>(st + 6 * p));
            s23 = __ldcs(reinterpret_cast<const float2*>(st + 6 * p + 2));
            s45 = __ldcs(reinterpret_cast<const float2*>(st + 6 * p + 4));
        }

        // Row-constant chain, with speculative adj prefetch off v.
        const int v = __ldg(nlv + row);
        if (act) {
            const float* pf = adj + (size_t)v * N + 2 * p;
            asm volatile("prefetch.global.L1 [%0];" :: "l"(pf));
        }
        const int   idx = __ldg(pidx + v);
        const float zx  = __ldg(coords + 2 * v);
        const float zy  = __ldg(coords + 2 * v + 1);

        const float* __restrict__ ar = adj + (size_t)idx * N;      // 8B aligned

        if (act) {
            const float2 aa = __ldg(reinterpret_cast<const float2*>(ar + 2 * p));

            float4* d = reinterpret_cast<float4*>(s_row + 12 * p); // 16B aligned
            d[0] = make_float4(s01.x, s01.y, s23.x, zx);
            d[1] = make_float4(zy,    aa.x,  s23.y, s45.x);
            d[2] = make_float4(s45.y, zx,    zy,    aa.y);
        }
        __syncwarp();
        asm volatile("fence.proxy.async.shared::cta;" ::: "memory");

        if (cnt > 0 && lane == 0) {
            const int c = min(32, cnt);
            const unsigned bytes = (unsigned)(c * 12 * sizeof(float));  // mult of 48
            float* gdst = orow + (size_t)start * 12;
            uint32_t saddr;
            asm("{ .reg .u64 tmp; cvta.to.shared.u64 tmp, %1; cvt.u32.u64 %0, tmp; }"
                : "=r"(saddr) : "l"(s_row + 12 * start));
            asm volatile(
                "cp.async.bulk.global.shared::cta.bulk_group [%0], [%1], %2;"
                :: "l"(gdst), "r"(saddr), "r"(bytes) : "memory");
            asm volatile("cp.async.bulk.commit_group;" ::: "memory");
        }

        // Odd-N tail node.
        if ((N & 1) && t == 0) {
            const int n = N - 1;
            float* dsc = orow + 6 * n;
            __stcs(dsc + 0, st[3 * n + 0]);
            __stcs(dsc + 1, st[3 * n + 1]);
            __stcs(dsc + 2, st[3 * n + 2]);
            __stcs(dsc + 3, zx);
            __stcs(dsc + 4, zy);
            __stcs(dsc + 5, ar[n]);
        }

        // Exit gate: smem READ completion only.
        if (lane == 0) {
            asm volatile("cp.async.bulk.wait_group.read 0;" ::: "memory");
        }
    } else {
        // Fallback: staged scalar copy with full-block sync.
        const int v   = __ldg(nlv + row);
        const int idx = __ldg(pidx + v);
        const float zx = __ldg(coords + 2 * v);
        const float zy = __ldg(coords + 2 * v + 1);
        const float* __restrict__ ar = adj + (size_t)idx * N;
        for (int n = t; n < N; n += blockDim.x) {
            float* d = s_row + 6 * n;
            d[0] = st[3 * n + 0];
            d[1] = st[3 * n + 1];
            d[2] = st[3 * n + 2];
            d[3] = zx;
            d[4] = zy;
            d[5] = ar[n];
        }
        __syncthreads();
        const int total = N * 6;
        for (int j = t; j < total; j += blockDim.x) {
            __stcs(orow + j, s_row[j]);
        }
    }
}

extern "C" void kernel_launch(void* const* d_in, const int* in_sizes, int n_in,
                              void* d_out, int out_size) {
    const float* state  = (const float*)d_in[0];
    const float* coords = (const float*)d_in[1];
    const float* adj    = (const float*)d_in[2];
    const int*   nlv    = (const int*)d_in[3];
    const int*   pidx   = (const int*)d_in[4];
    float*       out    = (float*)d_out;

    const int BA = in_sizes[3];            // B * A rows
    const int P  = in_sizes[4];            // patrol nodes
    const int N  = in_sizes[2] / P;        // graph size (adj is [P, N])

    const size_t smem = (size_t)N * 6 * sizeof(float);
    policy_gather_kernel<<<BA, 128, smem>>>(state, coords, adj, nlv, pidx, out, N);
}